// round 15
// baseline (speedup 1.0000x reference)
#include <cuda_runtime.h>
#include <math.h>

#define B_ 32
#define S_ 256
#define L_ 24
#define E_ 300
#define E_P 304          // E padded to multiple of 8 for GEMM
#define H_ 256
#define T_ 16
#define D_ 256
#define BS_ (B_*S_)      // 8192
#define G3H (3*H_)       // 768
#define H2 (2*H_)        // 512
#define H4 (4*H_)        // 1024
#define GRU_NBLK 64      // 32 per direction, 512 threads each
#define MCMB (B_*T_ + B_) // 544 combined topic+doc rows
#define HP 34            // smem pitch (4B-word stride 2*ks mod 32 -> conflict-free)

typedef unsigned long long ull;

// ---- packed f32x2 helpers (Blackwell dual-fp32; validated exact in R9) ----
#define FMA2(d, a, b) asm("fma.rn.f32x2 %0, %1, %2, %0;" : "+l"(d) : "l"(a), "l"(b))
#define ADD2(d, a, b) asm("add.rn.f32x2 %0, %1, %2;" : "=l"(d) : "l"(a), "l"(b))
__device__ __forceinline__ ull pack2(float v) {
    ull d; unsigned u = __float_as_uint(v);
    asm("mov.b64 %0, {%1, %1};" : "=l"(d) : "r"(u));
    return d;
}
__device__ __forceinline__ void unpack2(ull v, float& lo, float& hi) {
    unsigned a, b;
    asm("mov.b64 {%0, %1}, %2;" : "=r"(a), "=r"(b) : "l"(v));
    lo = __uint_as_float(a); hi = __uint_as_float(b);
}

// ------------------------- scratch (device globals; no runtime allocs) ----
__device__ float g_sent_vecs[BS_*E_P];
__device__ float g_WihT[2][E_P*G3H];
__device__ float g_gi[2][BS_*G3H];
__device__ float g_sent_rep[BS_*H2];
__device__ float g_h[2][2][H_*B_];        // TRANSPOSED: [dir][buf][c*32 + b]
__device__ float g_hT[2][B_*H_];          // b-major final hidden
__device__ float g_cmb[MCMB*H2];          // rows 0..511 topic_mat, 512..543 doc_vec
__device__ int   g_topic_id[BS_];
__device__ float g_sent_part[BS_*H4];     // sent_rep @ W_att[512:]
__device__ float g_part[MCMB*H4];         // cmb @ W_att[:512]
__device__ float g_sent_dna[BS_*D_];      // sent_rep @ W_dna[:512]
__device__ float g_cmb_dna[MCMB*D_];      // cmb @ W_dna[512:]
__device__ float g_sc[2][BS_];
__device__ float g_w[2][BS_];
// monotonic barrier sub-counters: [dir][sub], each on its own 128B line
__device__ unsigned g_cnt[2][8][32];

// ------------------------------------------------------------------- init
__global__ void init_kernel() {
    int idx = blockIdx.x * blockDim.x + threadIdx.x;
    if (idx < 2*2*H_*B_) ((float*)g_h)[idx] = 0.f;
    if (idx < 16) g_cnt[idx >> 3][idx & 7][0] = 0u;
}

// ------------------------------------------------- transpose Wih -> [E_P,3H]
__global__ void transpose_wih(const float* __restrict__ Wf,
                              const float* __restrict__ Wb) {
    int idx = blockIdx.x * blockDim.x + threadIdx.x;
    if (idx < E_P * G3H) {
        int c = idx / G3H, r = idx % G3H;
        float vf = 0.f, vb = 0.f;
        if (c < E_) { vf = Wf[r*E_ + c]; vb = Wb[r*E_ + c]; }
        g_WihT[0][c*G3H + r] = vf;
        g_WihT[1][c*G3H + r] = vb;
    }
}

// ------------------------------------- sent_vecs = mean over L embeddings
__global__ void embed_mean(const int* __restrict__ wid,
                           const float* __restrict__ emb) {
    int bs = blockIdx.x;
    __shared__ int sw[L_];
    if (threadIdx.x < L_) sw[threadIdx.x] = wid[bs*L_ + threadIdx.x];
    __syncthreads();
    const float inv = 1.f / (float)L_;
    for (int c = threadIdx.x; c < E_P; c += blockDim.x) {
        float s = 0.f;
        if (c < E_) {
#pragma unroll
            for (int l = 0; l < L_; l++)
                s += __ldg(&emb[(size_t)sw[l]*E_ + c]);
            s *= inv;
        }
        g_sent_vecs[(size_t)bs*E_P + c] = s;
    }
}

// ------------------------------------------------------------- SGEMM 128x128
// (scalar FFMA — R13 proven; both f32x2 variants regressed: R10 regs, R14 LDS)
template<bool HASB, bool DUAL>
__global__ void __launch_bounds__(256)
sgemm128(const float* __restrict__ A, const float* __restrict__ Bm0,
         const float* __restrict__ bias0, float* __restrict__ C0,
         const float* __restrict__ Bm1, const float* __restrict__ bias1,
         float* __restrict__ C1, int M, int N, int K) {
    const float* Bm   = (DUAL && blockIdx.z) ? Bm1   : Bm0;
    const float* bias = (DUAL && blockIdx.z) ? bias1 : bias0;
    float*       C    = (DUAL && blockIdx.z) ? C1    : C0;
    __shared__ float As[2][8][128];
    __shared__ float Bs[2][8][128];
    const int tid = threadIdx.x;
    const int bm = blockIdx.y * 128, bn = blockIdx.x * 128;
    const int tx = tid & 15, ty = tid >> 4;
    const int aRow = tid >> 1, aCol = (tid & 1) * 4;
    const int bRow = tid >> 5, bCol = (tid & 31) * 4;
    const bool aValid = (bm + aRow) < M;
    const float* Aptr = A + (size_t)(bm + aRow) * K + aCol;
    const float* Bptr = Bm + (size_t)bRow * N + bn + bCol;

    float acc[8][8];
#pragma unroll
    for (int i = 0; i < 8; i++)
#pragma unroll
        for (int j = 0; j < 8; j++) acc[i][j] = 0.f;

    float4 av = aValid ? *(const float4*)Aptr : make_float4(0.f,0.f,0.f,0.f);
    float4 bv = *(const float4*)Bptr;
    As[0][aCol+0][aRow] = av.x; As[0][aCol+1][aRow] = av.y;
    As[0][aCol+2][aRow] = av.z; As[0][aCol+3][aRow] = av.w;
    *(float4*)&Bs[0][bRow][bCol] = bv;
    __syncthreads();

    const int nStages = K >> 3;
    for (int s = 0; s < nStages; s++) {
        const int cur = s & 1, nxt = cur ^ 1;
        if (s + 1 < nStages) {
            av = aValid ? *(const float4*)(Aptr + (s+1)*8)
                        : make_float4(0.f,0.f,0.f,0.f);
            bv = *(const float4*)(Bptr + (size_t)(s+1)*8*N);
        }
#pragma unroll
        for (int kk = 0; kk < 8; kk++) {
            float4 a0 = *(const float4*)&As[cur][kk][ty*8];
            float4 a1 = *(const float4*)&As[cur][kk][ty*8+4];
            float4 b0 = *(const float4*)&Bs[cur][kk][tx*8];
            float4 b1 = *(const float4*)&Bs[cur][kk][tx*8+4];
            float a[8] = {a0.x,a0.y,a0.z,a0.w,a1.x,a1.y,a1.z,a1.w};
            float b[8] = {b0.x,b0.y,b0.z,b0.w,b1.x,b1.y,b1.z,b1.w};
#pragma unroll
            for (int i = 0; i < 8; i++)
#pragma unroll
                for (int j = 0; j < 8; j++) acc[i][j] += a[i]*b[j];
        }
        if (s + 1 < nStages) {
            As[nxt][aCol+0][aRow] = av.x; As[nxt][aCol+1][aRow] = av.y;
            As[nxt][aCol+2][aRow] = av.z; As[nxt][aCol+3][aRow] = av.w;
            *(float4*)&Bs[nxt][bRow][bCol] = bv;
        }
        __syncthreads();
    }

#pragma unroll
    for (int i = 0; i < 8; i++) {
        int m = bm + ty*8 + i;
        if (m < M) {
            float4 o0, o1;
#pragma unroll
            for (int j = 0; j < 8; j++) {
                float v = acc[i][j];
                if (HASB) v += bias[bn + tx*8 + j];
                if (j < 4) ((float*)&o0)[j] = v; else ((float*)&o1)[j-4] = v;
            }
            *(float4*)&C[(size_t)m*N + bn + tx*8]     = o0;
            *(float4*)&C[(size_t)m*N + bn + tx*8 + 4] = o1;
        }
    }
}

// --------------------------------------------------- persistent GRU kernel
// R13 algorithm, reshaped: 64 blocks x 512 threads (8 hidden cols/block).
// Halves per-step L2 h-broadcast traffic (2MB vs 4MB) and barrier arrivals.
// Per-thread work/registers identical to R13. thread map [bg:4][q:8][ks:16].
__global__ void __launch_bounds__(512) gru_kernel(
    const float* __restrict__ Whh_f, const float* __restrict__ Whh_b,
    const float* __restrict__ bhh_f, const float* __restrict__ bhh_b) {
    __shared__ float sh[H_ * HP];              // sh[k*HP + b], pitch 34
    const int tid = threadIdx.x;
    const int blk = blockIdx.x;
    const int dir = blk >> 5;                  // 0 fwd, 1 bwd (32 blocks each)
    const int dblk = blk & 31;
    const int cb  = dblk * 8;                  // 8 hidden cols per block
    const int bg  = tid >> 7;                  // 0..3 (batch group of 8)
    const int q   = (tid >> 4) & 7;            // 0..7 (local column)
    const int ks  = tid & 15;                  // 0..15 (k slice)
    const float* Whh = dir ? Whh_b : Whh_f;
    const float* bhh = dir ? bhh_b : bhh_f;
    const float* gi  = g_gi[dir];
    const int j = cb + q;

    ull w2[3][16];
#pragma unroll
    for (int ki = 0; ki < 16; ki++) {
        int kk = ks + 16*ki;
        w2[0][ki] = pack2(Whh[(0*H_ + j)*H_ + kk]);
        w2[1][ki] = pack2(Whh[(1*H_ + j)*H_ + kk]);
        w2[2][ki] = pack2(Whh[(2*H_ + j)*H_ + kk]);
    }
    const float bb0 = bhh[j], bb1 = bhh[H_ + j], bb2 = bhh[2*H_ + j];
    const bool wr = (ks < 4);
    const int bp = bg*8 + 2*ks;                // batch pair base (writers)

    volatile unsigned* cc[8];
#pragma unroll
    for (int u = 0; u < 8; u++) cc[u] = &g_cnt[dir][u][0];

    for (int i = 0; i < S_; i++) {
        const int t = dir ? (S_ - 1 - i) : i;
        const int cur = i & 1, nxt = cur ^ 1;

        float gir0=0.f, giz0=0.f, gin0=0.f, gir1=0.f, giz1=0.f, gin1=0.f;
        int row0 = 0, row1 = 0;
        if (wr) {
            row0 = bp*S_ + t; row1 = (bp+1)*S_ + t;
            gir0 = __ldg(&gi[(size_t)row0*G3H + j]);
            giz0 = __ldg(&gi[(size_t)row0*G3H + H_ + j]);
            gin0 = __ldg(&gi[(size_t)row0*G3H + 2*H_ + j]);
            gir1 = __ldg(&gi[(size_t)row1*G3H + j]);
            giz1 = __ldg(&gi[(size_t)row1*G3H + H_ + j]);
            gin1 = __ldg(&gi[(size_t)row1*G3H + 2*H_ + j]);
        }

        const float4* hb = (const float4*)g_h[dir][cur];
#pragma unroll
        for (int xi = 0; xi < 4; xi++) {
            int x = xi*512 + tid;              // float4 index, 2048 total
            float4 v = __ldcg(hb + x);
            int c = x >> 3, b4 = (x & 7) * 4;
            float* d = &sh[c*HP + b4];         // even offset -> float2 ok
            *(float2*)(d)     = make_float2(v.x, v.y);
            *(float2*)(d + 2) = make_float2(v.z, v.w);
        }
        __syncthreads();

        ull acc[4][3];
#pragma unroll
        for (int p = 0; p < 4; p++) { acc[p][0]=0ull; acc[p][1]=0ull; acc[p][2]=0ull; }
#pragma unroll
        for (int ki = 0; ki < 16; ki++) {
            int kk = ks + 16*ki;
            const ull* hrow = (const ull*)&sh[kk*HP + bg*8];
#pragma unroll
            for (int p = 0; p < 4; p++) {
                ull h2 = hrow[p];
                FMA2(acc[p][0], h2, w2[0][ki]);
                FMA2(acc[p][1], h2, w2[1][ki]);
                FMA2(acc[p][2], h2, w2[2][ki]);
            }
        }
        // butterfly-reduce the 16 k-slices (lane bits 0..3 -> within warp)
#pragma unroll
        for (int m = 1; m < 16; m <<= 1) {
#pragma unroll
            for (int p = 0; p < 4; p++) {
#pragma unroll
                for (int g = 0; g < 3; g++) {
                    ull o = __shfl_xor_sync(0xffffffffu, acc[p][g], m);
                    ADD2(acc[p][g], acc[p][g], o);
                }
            }
        }
        if (wr) {
            ull ar = (ks==0)?acc[0][0]:(ks==1)?acc[1][0]:(ks==2)?acc[2][0]:acc[3][0];
            ull az = (ks==0)?acc[0][1]:(ks==1)?acc[1][1]:(ks==2)?acc[2][1]:acc[3][1];
            ull an = (ks==0)?acc[0][2]:(ks==1)?acc[1][2]:(ks==2)?acc[2][2]:acc[3][2];
            float gr0, gr1, gz0, gz1, gn0, gn1;
            unpack2(ar, gr0, gr1); unpack2(az, gz0, gz1); unpack2(an, gn0, gn1);

            const float2 hold = *(const float2*)&sh[j*HP + bp];

            const float r0 = 1.f / (1.f + __expf(-(gir0 + gr0 + bb0)));
            const float z0 = 1.f / (1.f + __expf(-(giz0 + gz0 + bb1)));
            const float n0 = tanhf(gin0 + r0 * (gn0 + bb2));
            const float h0 = (1.f - z0)*n0 + z0*hold.x;

            const float r1 = 1.f / (1.f + __expf(-(gir1 + gr1 + bb0)));
            const float z1 = 1.f / (1.f + __expf(-(giz1 + gz1 + bb1)));
            const float n1 = tanhf(gin1 + r1 * (gn1 + bb2));
            const float h1 = (1.f - z1)*n1 + z1*hold.y;

            __stcg((float2*)&g_h[dir][nxt][j*32 + bp], make_float2(h0, h1));
            g_sent_rep[(size_t)row0*H2 + dir*H_ + j] = h0;
            g_sent_rep[(size_t)row1*H2 + dir*H_ + j] = h1;
            if (i == S_-1) {
                g_hT[dir][bp*H_ + j]     = h0;
                g_hT[dir][(bp+1)*H_ + j] = h1;
            }
        }
        if (i != S_-1) {
            // barrier: 8 counters/dir, 4 arrivals each (32 blocks/dir),
            // single tid0 poller with MLP-parallel volatile reads.
            __threadfence();
            __syncthreads();
            if (tid == 0) {
                atomicAdd(&g_cnt[dir][dblk & 7][0], 1u);
                const unsigned target = (unsigned)(i + 1) * 4u;
                unsigned v0,v1,v2,v3,v4,v5,v6,v7;
                do {
                    v0 = *cc[0]; v1 = *cc[1]; v2 = *cc[2]; v3 = *cc[3];
                    v4 = *cc[4]; v5 = *cc[5]; v6 = *cc[6]; v7 = *cc[7];
                } while (v0 < target || v1 < target || v2 < target ||
                         v3 < target || v4 < target || v5 < target ||
                         v6 < target || v7 < target);
            }
            __syncthreads();
        }
    }
}

// ----------------------------- combined (topic_mat ++ doc_vec) + topic_id
__global__ void prep_kernel(const int* __restrict__ tse) {
    const int gstride = gridDim.x * blockDim.x;
    const int gtid = blockIdx.x * blockDim.x + threadIdx.x;
    for (int idx = gtid; idx < B_*H2; idx += gstride) {
        int d = idx >> 13; int rem = idx & 8191;
        g_cmb[B_*T_*H2 + idx] = g_hT[d][rem];
    }
    for (int idx = gtid; idx < B_*T_*H2; idx += gstride) {
        int c = idx & 511; int t = (idx >> 9) & 15; int b = idx >> 13;
        int st = tse[(b*T_ + t)*2 + 0], en = tse[(b*T_ + t)*2 + 1];
        int p1, p2;
        if (c < H_) { p1 = en;  p2 = st - 1; }
        else        { p1 = st;  p2 = en + 1; }
        p1 = min(max(p1, 0), S_+1); p2 = min(max(p2, 0), S_+1);
        float v1 = (p1 >= 1 && p1 <= S_) ? g_sent_rep[(size_t)(b*S_ + p1-1)*H2 + c] : 0.f;
        float v2 = (p2 >= 1 && p2 <= S_) ? g_sent_rep[(size_t)(b*S_ + p2-1)*H2 + c] : 0.f;
        g_cmb[idx] = v1 - v2;
    }
    for (int idx = gtid; idx < BS_; idx += gstride) {
        int b = idx >> 8, s = idx & 255;
        int t = 0;
        while (t < T_ && tse[(b*T_ + t)*2 + 1] < s + 1) t++;
        if (t >= T_) t = T_ - 1;
        g_topic_id[idx] = t;
    }
}

// ---------------- fused: scores = tanh(sent_part + {doc|topic}_part) . v
__global__ void __launch_bounds__(256) score_fused(const float* __restrict__ v) {
    const int row = blockIdx.x;
    const int b = row >> 8;
    const int bt = b*T_ + g_topic_id[row];
    const float* sp = &g_sent_part[(size_t)row*H4];
    const float* dp = &g_part[(size_t)(B_*T_ + b)*H4];
    const float* tp = &g_part[(size_t)bt*H4];
    float s0 = 0.f, s1 = 0.f;
    for (int c = threadIdx.x; c < H4; c += 256) {
        float s = sp[c], vv = v[c];
        s0 += tanhf(s + dp[c]) * vv;
        s1 += tanhf(s + tp[c]) * vv;
    }
    __shared__ float r0[256], r1[256];
    r0[threadIdx.x] = s0; r1[threadIdx.x] = s1;
    __syncthreads();
    for (int m = 128; m; m >>= 1) {
        if (threadIdx.x < m) {
            r0[threadIdx.x] += r0[threadIdx.x + m];
            r1[threadIdx.x] += r1[threadIdx.x + m];
        }
        __syncthreads();
    }
    if (threadIdx.x == 0) { g_sc[0][row] = r0[0]; g_sc[1][row] = r1[0]; }
}

// ------------------------------------------------------ softmax over S
__global__ void softmax_kernel() {
    const int type = blockIdx.x >> 5, b = blockIdx.x & 31;
    const int s = threadIdx.x;
    __shared__ float sm[256];
    float x = g_sc[type][b*S_ + s];
    sm[s] = x; __syncthreads();
    for (int m = 128; m; m >>= 1) { if (s < m) sm[s] = fmaxf(sm[s], sm[s + m]); __syncthreads(); }
    float mx = sm[0]; __syncthreads();
    float e = __expf(x - mx);
    sm[s] = e; __syncthreads();
    for (int m = 128; m; m >>= 1) { if (s < m) sm[s] += sm[s + m]; __syncthreads(); }
    g_w[type][b*S_ + s] = e / sm[0];
}

// ------ fused: h=relu(sent_dna + wd*doc_dna + wt*topic_dna + b); out=h.Wout
__global__ void __launch_bounds__(256) final_fused(
    const float* __restrict__ b_dna, const float* __restrict__ Wout,
    const float* __restrict__ bout, float* __restrict__ out) {
    const int row = blockIdx.x;
    const int b = row >> 8;
    const int bt = b*T_ + g_topic_id[row];
    const int c = threadIdx.x;
    const float wd = g_w[0][row], wt = g_w[1][row];
    float h = g_sent_dna[(size_t)row*D_ + c]
            + wd * g_cmb_dna[(size_t)(B_*T_ + b)*D_ + c]
            + wt * g_cmb_dna[(size_t)bt*D_ + c]
            + b_dna[c];
    h = fmaxf(h, 0.f);
    float s = h * Wout[c];
    __shared__ float r[256];
    r[c] = s; __syncthreads();
    for (int m = 128; m; m >>= 1) {
        if (c < m) r[c] += r[c + m];
        __syncthreads();
    }
    if (c == 0) out[row] = r[0] + bout[0];
}

// ------------------------------------------------------------------ host
extern "C" void kernel_launch(void* const* d_in, const int* in_sizes, int n_in,
                              void* d_out, int out_size) {
    const int*   word_ids = (const int*)  d_in[0];
    const int*   tse      = (const int*)  d_in[1];
    const float* emb      = (const float*)d_in[2];
    const float* Wih_f    = (const float*)d_in[3];
    const float* Whh_f    = (const float*)d_in[4];
    const float* bih_f    = (const float*)d_in[5];
    const float* bhh_f    = (const float*)d_in[6];
    const float* Wih_b    = (const float*)d_in[7];
    const float* Whh_b    = (const float*)d_in[8];
    const float* bih_b    = (const float*)d_in[9];
    const float* bhh_b    = (const float*)d_in[10];
    const float* W_att    = (const float*)d_in[11];
    const float* v_att    = (const float*)d_in[12];
    const float* W_dna    = (const float*)d_in[13];
    const float* b_dna    = (const float*)d_in[14];
    const float* W_out    = (const float*)d_in[15];
    const float* b_out    = (const float*)d_in[16];
    float* out = (float*)d_out;

    float *p_sv, *p_wt, *p_gi, *p_sr, *p_cmb;
    float *p_spart, *p_part, *p_sdna, *p_cdna;
    cudaGetSymbolAddress((void**)&p_sv,   g_sent_vecs);
    cudaGetSymbolAddress((void**)&p_wt,   g_WihT);
    cudaGetSymbolAddress((void**)&p_gi,   g_gi);
    cudaGetSymbolAddress((void**)&p_sr,   g_sent_rep);
    cudaGetSymbolAddress((void**)&p_cmb,  g_cmb);
    cudaGetSymbolAddress((void**)&p_spart, g_sent_part);
    cudaGetSymbolAddress((void**)&p_part,  g_part);
    cudaGetSymbolAddress((void**)&p_sdna,  g_sent_dna);
    cudaGetSymbolAddress((void**)&p_cdna,  g_cmb_dna);

    init_kernel<<<128, 256>>>();
    transpose_wih<<<(E_P*G3H + 255)/256, 256>>>(Wih_f, Wih_b);
    embed_mean<<<BS_, 128>>>(word_ids, emb);

    // gi = sent_vecs @ Wih^T + bih  (both directions fused via gridDim.z)
    sgemm128<true, true><<<dim3(G3H/128, BS_/128, 2), 256>>>(
        p_sv, p_wt, bih_f, p_gi,
        p_wt + E_P*G3H, bih_b, p_gi + BS_*G3H, BS_, G3H, E_P);

    gru_kernel<<<GRU_NBLK, 512>>>(Whh_f, Whh_b, bhh_f, bhh_b);

    prep_kernel<<<256, 256>>>(tse);

    // attention pre-GEMMs (split W_att by row halves; doc+topic combined)
    sgemm128<false, false><<<dim3(H4/128, BS_/128), 256>>>(
        p_sr, W_att + (size_t)H2*H4, nullptr, p_spart,
        nullptr, nullptr, nullptr, BS_, H4, H2);
    sgemm128<false, false><<<dim3(H4/128, (MCMB+127)/128), 256>>>(
        p_cmb, W_att, nullptr, p_part,
        nullptr, nullptr, nullptr, MCMB, H4, H2);

    score_fused<<<BS_, 256>>>(v_att);
    softmax_kernel<<<64, 256>>>();

    // dna pre-GEMMs (split W_dna by row halves; doc+topic combined)
    sgemm128<false, false><<<dim3(D_/128, BS_/128), 256>>>(
        p_sr, W_dna, nullptr, p_sdna,
        nullptr, nullptr, nullptr, BS_, D_, H2);
    sgemm128<false, false><<<dim3(D_/128, (MCMB+127)/128), 256>>>(
        p_cmb, W_dna + (size_t)H2*D_, nullptr, p_cdna,
        nullptr, nullptr, nullptr, MCMB, D_, H2);

    final_fused<<<BS_, 256>>>(b_dna, W_out, b_out, out);
}

// round 16
// speedup vs baseline: 1.2039x; 1.2039x over previous
#include <cuda_runtime.h>
#include <math.h>

#define B_ 32
#define S_ 256
#define L_ 24
#define E_ 300
#define E_P 304          // E padded to multiple of 8 for GEMM
#define H_ 256
#define T_ 16
#define D_ 256
#define BS_ (B_*S_)      // 8192
#define G3H (3*H_)       // 768
#define H2 (2*H_)        // 512
#define H4 (4*H_)        // 1024
#define GRU_NBLK 128     // 64 per direction (R13 proven shape)
#define MCMB (B_*T_ + B_) // 544 combined topic+doc rows
#define HP 34            // smem pitch (4B-word stride 2*ks mod 32 -> conflict-free)

typedef unsigned long long ull;

// ---- packed f32x2 helpers (Blackwell dual-fp32; validated exact in R9) ----
#define FMA2(d, a, b) asm("fma.rn.f32x2 %0, %1, %2, %0;" : "+l"(d) : "l"(a), "l"(b))
#define ADD2(d, a, b) asm("add.rn.f32x2 %0, %1, %2;" : "=l"(d) : "l"(a), "l"(b))
__device__ __forceinline__ ull pack2(float v) {
    ull d; unsigned u = __float_as_uint(v);
    asm("mov.b64 %0, {%1, %1};" : "=l"(d) : "r"(u));
    return d;
}
__device__ __forceinline__ void unpack2(ull v, float& lo, float& hi) {
    unsigned a, b;
    asm("mov.b64 {%0, %1}, %2;" : "=r"(a), "=r"(b) : "l"(v));
    lo = __uint_as_float(a); hi = __uint_as_float(b);
}

// ------------------------- scratch (device globals; no runtime allocs) ----
__device__ float g_sent_vecs[BS_*E_P];
__device__ float g_WihT[2][E_P*G3H];
__device__ float g_gi[2][BS_*G3H];
__device__ float g_sent_rep[BS_*H2];
__device__ float g_h[2][2][H_*B_];        // TRANSPOSED: [dir][buf][c*32 + b]
__device__ float g_hT[2][B_*H_];          // b-major final hidden
__device__ float g_cmb[MCMB*H2];          // rows 0..511 topic_mat, 512..543 doc_vec
__device__ int   g_topic_id[BS_];
__device__ float g_sent_part[BS_*H4];     // sent_rep @ W_att[512:]
__device__ float g_part[MCMB*H4];         // cmb @ W_att[:512]
__device__ float g_sent_dna[BS_*D_];      // sent_rep @ W_dna[:512]
__device__ float g_cmb_dna[MCMB*D_];      // cmb @ W_dna[512:]
__device__ float g_sc[2][BS_];
__device__ float g_w[2][BS_];
// monotonic barrier sub-counters: [dir][sub], each on its own 128B line
__device__ unsigned g_cnt[2][8][32];

// ------------------------------------------------------------------- init
__global__ void init_kernel() {
    int idx = blockIdx.x * blockDim.x + threadIdx.x;
    if (idx < 2*2*H_*B_) ((float*)g_h)[idx] = 0.f;
    if (idx < 16) g_cnt[idx >> 3][idx & 7][0] = 0u;
}

// ------------------------------------------------- transpose Wih -> [E_P,3H]
__global__ void transpose_wih(const float* __restrict__ Wf,
                              const float* __restrict__ Wb) {
    int idx = blockIdx.x * blockDim.x + threadIdx.x;
    if (idx < E_P * G3H) {
        int c = idx / G3H, r = idx % G3H;
        float vf = 0.f, vb = 0.f;
        if (c < E_) { vf = Wf[r*E_ + c]; vb = Wb[r*E_ + c]; }
        g_WihT[0][c*G3H + r] = vf;
        g_WihT[1][c*G3H + r] = vb;
    }
}

// --------------------- sent_vecs = mean over L embeddings (float4 gathers)
__global__ void embed_mean(const int* __restrict__ wid,
                           const float* __restrict__ emb) {
    int bs = blockIdx.x;
    __shared__ int sw[L_];
    if (threadIdx.x < L_) sw[threadIdx.x] = wid[bs*L_ + threadIdx.x];
    __syncthreads();
    const float inv = 1.f / (float)L_;
    // 76 float4 columns: 0..74 real (E=300=75*4, rows 16B-aligned), 75 = pad
    for (int c4 = threadIdx.x; c4 < E_P/4; c4 += blockDim.x) {
        float4 s = make_float4(0.f, 0.f, 0.f, 0.f);
        if (c4 < E_/4) {
#pragma unroll
            for (int l = 0; l < L_; l++) {
                float4 v = __ldg((const float4*)(emb + (size_t)sw[l]*E_) + c4);
                s.x += v.x; s.y += v.y; s.z += v.z; s.w += v.w;
            }
            s.x *= inv; s.y *= inv; s.z *= inv; s.w *= inv;
        }
        *(float4*)(g_sent_vecs + (size_t)bs*E_P + c4*4) = s;
    }
}

// ------------------------------------------------------------- SGEMM 128x128
// (scalar FFMA — R13 proven; f32x2 variants regressed: R10 regs, R14 LDS)
template<bool HASB, bool DUAL>
__global__ void __launch_bounds__(256)
sgemm128(const float* __restrict__ A, const float* __restrict__ Bm0,
         const float* __restrict__ bias0, float* __restrict__ C0,
         const float* __restrict__ Bm1, const float* __restrict__ bias1,
         float* __restrict__ C1, int M, int N, int K) {
    const float* Bm   = (DUAL && blockIdx.z) ? Bm1   : Bm0;
    const float* bias = (DUAL && blockIdx.z) ? bias1 : bias0;
    float*       C    = (DUAL && blockIdx.z) ? C1    : C0;
    __shared__ float As[2][8][128];
    __shared__ float Bs[2][8][128];
    const int tid = threadIdx.x;
    const int bm = blockIdx.y * 128, bn = blockIdx.x * 128;
    const int tx = tid & 15, ty = tid >> 4;
    const int aRow = tid >> 1, aCol = (tid & 1) * 4;
    const int bRow = tid >> 5, bCol = (tid & 31) * 4;
    const bool aValid = (bm + aRow) < M;
    const float* Aptr = A + (size_t)(bm + aRow) * K + aCol;
    const float* Bptr = Bm + (size_t)bRow * N + bn + bCol;

    float acc[8][8];
#pragma unroll
    for (int i = 0; i < 8; i++)
#pragma unroll
        for (int j = 0; j < 8; j++) acc[i][j] = 0.f;

    float4 av = aValid ? *(const float4*)Aptr : make_float4(0.f,0.f,0.f,0.f);
    float4 bv = *(const float4*)Bptr;
    As[0][aCol+0][aRow] = av.x; As[0][aCol+1][aRow] = av.y;
    As[0][aCol+2][aRow] = av.z; As[0][aCol+3][aRow] = av.w;
    *(float4*)&Bs[0][bRow][bCol] = bv;
    __syncthreads();

    const int nStages = K >> 3;
    for (int s = 0; s < nStages; s++) {
        const int cur = s & 1, nxt = cur ^ 1;
        if (s + 1 < nStages) {
            av = aValid ? *(const float4*)(Aptr + (s+1)*8)
                        : make_float4(0.f,0.f,0.f,0.f);
            bv = *(const float4*)(Bptr + (size_t)(s+1)*8*N);
        }
#pragma unroll
        for (int kk = 0; kk < 8; kk++) {
            float4 a0 = *(const float4*)&As[cur][kk][ty*8];
            float4 a1 = *(const float4*)&As[cur][kk][ty*8+4];
            float4 b0 = *(const float4*)&Bs[cur][kk][tx*8];
            float4 b1 = *(const float4*)&Bs[cur][kk][tx*8+4];
            float a[8] = {a0.x,a0.y,a0.z,a0.w,a1.x,a1.y,a1.z,a1.w};
            float b[8] = {b0.x,b0.y,b0.z,b0.w,b1.x,b1.y,b1.z,b1.w};
#pragma unroll
            for (int i = 0; i < 8; i++)
#pragma unroll
                for (int j = 0; j < 8; j++) acc[i][j] += a[i]*b[j];
        }
        if (s + 1 < nStages) {
            As[nxt][aCol+0][aRow] = av.x; As[nxt][aCol+1][aRow] = av.y;
            As[nxt][aCol+2][aRow] = av.z; As[nxt][aCol+3][aRow] = av.w;
            *(float4*)&Bs[nxt][bRow][bCol] = bv;
        }
        __syncthreads();
    }

#pragma unroll
    for (int i = 0; i < 8; i++) {
        int m = bm + ty*8 + i;
        if (m < M) {
            float4 o0, o1;
#pragma unroll
            for (int j = 0; j < 8; j++) {
                float v = acc[i][j];
                if (HASB) v += bias[bn + tx*8 + j];
                if (j < 4) ((float*)&o0)[j] = v; else ((float*)&o1)[j-4] = v;
            }
            *(float4*)&C[(size_t)m*N + bn + tx*8]     = o0;
            *(float4*)&C[(size_t)m*N + bn + tx*8 + 4] = o1;
        }
    }
}

// --------------------------------------------------- persistent GRU kernel
// == R13 (128 blocks x 256 thr, pitch 34, 8 counters/dir) with:
//  - __threadfence predicated on writers (only they have pending stores;
//    tid0 is a writer so the release chain is unchanged)
//  - sent_rep stores moved after the arrival (overlap the poll)
__global__ void __launch_bounds__(256) gru_kernel(
    const float* __restrict__ Whh_f, const float* __restrict__ Whh_b,
    const float* __restrict__ bhh_f, const float* __restrict__ bhh_b) {
    __shared__ float sh[H_ * HP];              // sh[k*HP + b], pitch 34
    const int tid = threadIdx.x;
    const int blk = blockIdx.x;
    const int dir = blk >> 6;                  // 0 fwd, 1 bwd
    const int dblk = blk & 63;
    const int cb  = dblk * 4;                  // 4 hidden cols per block
    const int bg  = tid >> 6;                  // 0..3 (batch group of 8)
    const int q   = (tid >> 4) & 3;            // 0..3 (local column)
    const int ks  = tid & 15;                  // 0..15 (k slice)
    const float* Whh = dir ? Whh_b : Whh_f;
    const float* bhh = dir ? bhh_b : bhh_f;
    const float* gi  = g_gi[dir];
    const int j = cb + q;

    ull w2[3][16];
#pragma unroll
    for (int ki = 0; ki < 16; ki++) {
        int kk = ks + 16*ki;
        w2[0][ki] = pack2(Whh[(0*H_ + j)*H_ + kk]);
        w2[1][ki] = pack2(Whh[(1*H_ + j)*H_ + kk]);
        w2[2][ki] = pack2(Whh[(2*H_ + j)*H_ + kk]);
    }
    const float bb0 = bhh[j], bb1 = bhh[H_ + j], bb2 = bhh[2*H_ + j];
    const bool wr = (ks < 4);
    const int bp = bg*8 + 2*ks;                // batch pair base (writers)

    volatile unsigned* cc[8];
#pragma unroll
    for (int u = 0; u < 8; u++) cc[u] = &g_cnt[dir][u][0];

    for (int i = 0; i < S_; i++) {
        const int t = dir ? (S_ - 1 - i) : i;
        const int cur = i & 1, nxt = cur ^ 1;

        float gir0=0.f, giz0=0.f, gin0=0.f, gir1=0.f, giz1=0.f, gin1=0.f;
        int row0 = 0, row1 = 0;
        if (wr) {
            row0 = bp*S_ + t; row1 = (bp+1)*S_ + t;
            gir0 = __ldg(&gi[(size_t)row0*G3H + j]);
            giz0 = __ldg(&gi[(size_t)row0*G3H + H_ + j]);
            gin0 = __ldg(&gi[(size_t)row0*G3H + 2*H_ + j]);
            gir1 = __ldg(&gi[(size_t)row1*G3H + j]);
            giz1 = __ldg(&gi[(size_t)row1*G3H + H_ + j]);
            gin1 = __ldg(&gi[(size_t)row1*G3H + 2*H_ + j]);
        }

        const float4* hb = (const float4*)g_h[dir][cur];
#pragma unroll
        for (int xi = 0; xi < 8; xi++) {
            int x = xi*256 + tid;              // float4 index, 2048 total
            float4 v = __ldcg(hb + x);
            int c = x >> 3, b4 = (x & 7) * 4;
            float* d = &sh[c*HP + b4];         // even offset -> float2 ok
            *(float2*)(d)     = make_float2(v.x, v.y);
            *(float2*)(d + 2) = make_float2(v.z, v.w);
        }
        __syncthreads();

        ull acc[4][3];
#pragma unroll
        for (int p = 0; p < 4; p++) { acc[p][0]=0ull; acc[p][1]=0ull; acc[p][2]=0ull; }
#pragma unroll
        for (int ki = 0; ki < 16; ki++) {
            int kk = ks + 16*ki;
            const ull* hrow = (const ull*)&sh[kk*HP + bg*8];
#pragma unroll
            for (int p = 0; p < 4; p++) {
                ull h2 = hrow[p];
                FMA2(acc[p][0], h2, w2[0][ki]);
                FMA2(acc[p][1], h2, w2[1][ki]);
                FMA2(acc[p][2], h2, w2[2][ki]);
            }
        }
#pragma unroll
        for (int m = 1; m < 16; m <<= 1) {
#pragma unroll
            for (int p = 0; p < 4; p++) {
#pragma unroll
                for (int g = 0; g < 3; g++) {
                    ull o = __shfl_xor_sync(0xffffffffu, acc[p][g], m);
                    ADD2(acc[p][g], acc[p][g], o);
                }
            }
        }
        float h0 = 0.f, h1 = 0.f;
        if (wr) {
            ull ar = (ks==0)?acc[0][0]:(ks==1)?acc[1][0]:(ks==2)?acc[2][0]:acc[3][0];
            ull az = (ks==0)?acc[0][1]:(ks==1)?acc[1][1]:(ks==2)?acc[2][1]:acc[3][1];
            ull an = (ks==0)?acc[0][2]:(ks==1)?acc[1][2]:(ks==2)?acc[2][2]:acc[3][2];
            float gr0, gr1, gz0, gz1, gn0, gn1;
            unpack2(ar, gr0, gr1); unpack2(az, gz0, gz1); unpack2(an, gn0, gn1);

            const float2 hold = *(const float2*)&sh[j*HP + bp];

            const float r0 = 1.f / (1.f + __expf(-(gir0 + gr0 + bb0)));
            const float z0 = 1.f / (1.f + __expf(-(giz0 + gz0 + bb1)));
            const float n0 = tanhf(gin0 + r0 * (gn0 + bb2));
            h0 = (1.f - z0)*n0 + z0*hold.x;

            const float r1 = 1.f / (1.f + __expf(-(gir1 + gr1 + bb0)));
            const float z1 = 1.f / (1.f + __expf(-(giz1 + gz1 + bb1)));
            const float n1 = tanhf(gin1 + r1 * (gn1 + bb2));
            h1 = (1.f - z1)*n1 + z1*hold.y;

            __stcg((float2*)&g_h[dir][nxt][j*32 + bp], make_float2(h0, h1));
        }
        if (i != S_-1) {
            // release: only writers have pending global stores to drain
            if (wr) __threadfence();
            __syncthreads();
            if (tid == 0) atomicAdd(&g_cnt[dir][dblk & 7][0], 1u);
            // sent_rep stores overlap the poll (not read in-kernel)
            if (wr) {
                g_sent_rep[(size_t)row0*H2 + dir*H_ + j] = h0;
                g_sent_rep[(size_t)row1*H2 + dir*H_ + j] = h1;
            }
            if (tid == 0) {
                const unsigned target = (unsigned)(i + 1) * 8u;
                unsigned v0,v1,v2,v3,v4,v5,v6,v7;
                do {
                    v0 = *cc[0]; v1 = *cc[1]; v2 = *cc[2]; v3 = *cc[3];
                    v4 = *cc[4]; v5 = *cc[5]; v6 = *cc[6]; v7 = *cc[7];
                } while (v0 < target || v1 < target || v2 < target ||
                         v3 < target || v4 < target || v5 < target ||
                         v6 < target || v7 < target);
            }
            __syncthreads();
        } else if (wr) {
            g_sent_rep[(size_t)row0*H2 + dir*H_ + j] = h0;
            g_sent_rep[(size_t)row1*H2 + dir*H_ + j] = h1;
            g_hT[dir][bp*H_ + j]     = h0;
            g_hT[dir][(bp+1)*H_ + j] = h1;
        }
    }
}

// ----------------------------- combined (topic_mat ++ doc_vec) + topic_id
__global__ void prep_kernel(const int* __restrict__ tse) {
    const int gstride = gridDim.x * blockDim.x;
    const int gtid = blockIdx.x * blockDim.x + threadIdx.x;
    for (int idx = gtid; idx < B_*H2; idx += gstride) {
        int d = idx >> 13; int rem = idx & 8191;
        g_cmb[B_*T_*H2 + idx] = g_hT[d][rem];
    }
    for (int idx = gtid; idx < B_*T_*H2; idx += gstride) {
        int c = idx & 511; int t = (idx >> 9) & 15; int b = idx >> 13;
        int st = tse[(b*T_ + t)*2 + 0], en = tse[(b*T_ + t)*2 + 1];
        int p1, p2;
        if (c < H_) { p1 = en;  p2 = st - 1; }
        else        { p1 = st;  p2 = en + 1; }
        p1 = min(max(p1, 0), S_+1); p2 = min(max(p2, 0), S_+1);
        float v1 = (p1 >= 1 && p1 <= S_) ? g_sent_rep[(size_t)(b*S_ + p1-1)*H2 + c] : 0.f;
        float v2 = (p2 >= 1 && p2 <= S_) ? g_sent_rep[(size_t)(b*S_ + p2-1)*H2 + c] : 0.f;
        g_cmb[idx] = v1 - v2;
    }
    for (int idx = gtid; idx < BS_; idx += gstride) {
        int b = idx >> 8, s = idx & 255;
        int t = 0;
        while (t < T_ && tse[(b*T_ + t)*2 + 1] < s + 1) t++;
        if (t >= T_) t = T_ - 1;
        g_topic_id[idx] = t;
    }
}

// ---------------- fused: scores = tanh(sent_part + {doc|topic}_part) . v
__global__ void __launch_bounds__(256) score_fused(const float* __restrict__ v) {
    const int row = blockIdx.x;
    const int b = row >> 8;
    const int bt = b*T_ + g_topic_id[row];
    const float* sp = &g_sent_part[(size_t)row*H4];
    const float* dp = &g_part[(size_t)(B_*T_ + b)*H4];
    const float* tp = &g_part[(size_t)bt*H4];
    float s0 = 0.f, s1 = 0.f;
    for (int c = threadIdx.x; c < H4; c += 256) {
        float s = sp[c], vv = v[c];
        s0 += tanhf(s + dp[c]) * vv;
        s1 += tanhf(s + tp[c]) * vv;
    }
    __shared__ float r0[256], r1[256];
    r0[threadIdx.x] = s0; r1[threadIdx.x] = s1;
    __syncthreads();
    for (int m = 128; m; m >>= 1) {
        if (threadIdx.x < m) {
            r0[threadIdx.x] += r0[threadIdx.x + m];
            r1[threadIdx.x] += r1[threadIdx.x + m];
        }
        __syncthreads();
    }
    if (threadIdx.x == 0) { g_sc[0][row] = r0[0]; g_sc[1][row] = r1[0]; }
}

// ------------------------------------------------------ softmax over S
__global__ void softmax_kernel() {
    const int type = blockIdx.x >> 5, b = blockIdx.x & 31;
    const int s = threadIdx.x;
    __shared__ float sm[256];
    float x = g_sc[type][b*S_ + s];
    sm[s] = x; __syncthreads();
    for (int m = 128; m; m >>= 1) { if (s < m) sm[s] = fmaxf(sm[s], sm[s + m]); __syncthreads(); }
    float mx = sm[0]; __syncthreads();
    float e = __expf(x - mx);
    sm[s] = e; __syncthreads();
    for (int m = 128; m; m >>= 1) { if (s < m) sm[s] += sm[s + m]; __syncthreads(); }
    g_w[type][b*S_ + s] = e / sm[0];
}

// ------ fused: h=relu(sent_dna + wd*doc_dna + wt*topic_dna + b); out=h.Wout
__global__ void __launch_bounds__(256) final_fused(
    const float* __restrict__ b_dna, const float* __restrict__ Wout,
    const float* __restrict__ bout, float* __restrict__ out) {
    const int row = blockIdx.x;
    const int b = row >> 8;
    const int bt = b*T_ + g_topic_id[row];
    const int c = threadIdx.x;
    const float wd = g_w[0][row], wt = g_w[1][row];
    float h = g_sent_dna[(size_t)row*D_ + c]
            + wd * g_cmb_dna[(size_t)(B_*T_ + b)*D_ + c]
            + wt * g_cmb_dna[(size_t)bt*D_ + c]
            + b_dna[c];
    h = fmaxf(h, 0.f);
    float s = h * Wout[c];
    __shared__ float r[256];
    r[c] = s; __syncthreads();
    for (int m = 128; m; m >>= 1) {
        if (c < m) r[c] += r[c + m];
        __syncthreads();
    }
    if (c == 0) out[row] = r[0] + bout[0];
}

// ------------------------------------------------------------------ host
extern "C" void kernel_launch(void* const* d_in, const int* in_sizes, int n_in,
                              void* d_out, int out_size) {
    const int*   word_ids = (const int*)  d_in[0];
    const int*   tse      = (const int*)  d_in[1];
    const float* emb      = (const float*)d_in[2];
    const float* Wih_f    = (const float*)d_in[3];
    const float* Whh_f    = (const float*)d_in[4];
    const float* bih_f    = (const float*)d_in[5];
    const float* bhh_f    = (const float*)d_in[6];
    const float* Wih_b    = (const float*)d_in[7];
    const float* Whh_b    = (const float*)d_in[8];
    const float* bih_b    = (const float*)d_in[9];
    const float* bhh_b    = (const float*)d_in[10];
    const float* W_att    = (const float*)d_in[11];
    const float* v_att    = (const float*)d_in[12];
    const float* W_dna    = (const float*)d_in[13];
    const float* b_dna    = (const float*)d_in[14];
    const float* W_out    = (const float*)d_in[15];
    const float* b_out    = (const float*)d_in[16];
    float* out = (float*)d_out;

    float *p_sv, *p_wt, *p_gi, *p_sr, *p_cmb;
    float *p_spart, *p_part, *p_sdna, *p_cdna;
    cudaGetSymbolAddress((void**)&p_sv,   g_sent_vecs);
    cudaGetSymbolAddress((void**)&p_wt,   g_WihT);
    cudaGetSymbolAddress((void**)&p_gi,   g_gi);
    cudaGetSymbolAddress((void**)&p_sr,   g_sent_rep);
    cudaGetSymbolAddress((void**)&p_cmb,  g_cmb);
    cudaGetSymbolAddress((void**)&p_spart, g_sent_part);
    cudaGetSymbolAddress((void**)&p_part,  g_part);
    cudaGetSymbolAddress((void**)&p_sdna,  g_sent_dna);
    cudaGetSymbolAddress((void**)&p_cdna,  g_cmb_dna);

    init_kernel<<<128, 256>>>();
    transpose_wih<<<(E_P*G3H + 255)/256, 256>>>(Wih_f, Wih_b);
    embed_mean<<<BS_, 96>>>(word_ids, emb);

    // gi = sent_vecs @ Wih^T + bih  (both directions fused via gridDim.z)
    sgemm128<true, true><<<dim3(G3H/128, BS_/128, 2), 256>>>(
        p_sv, p_wt, bih_f, p_gi,
        p_wt + E_P*G3H, bih_b, p_gi + BS_*G3H, BS_, G3H, E_P);

    gru_kernel<<<GRU_NBLK, 256>>>(Whh_f, Whh_b, bhh_f, bhh_b);

    prep_kernel<<<256, 256>>>(tse);

    // attention pre-GEMMs (split W_att by row halves; doc+topic combined)
    sgemm128<false, false><<<dim3(H4/128, BS_/128), 256>>>(
        p_sr, W_att + (size_t)H2*H4, nullptr, p_spart,
        nullptr, nullptr, nullptr, BS_, H4, H2);
    sgemm128<false, false><<<dim3(H4/128, (MCMB+127)/128), 256>>>(
        p_cmb, W_att, nullptr, p_part,
        nullptr, nullptr, nullptr, MCMB, H4, H2);

    score_fused<<<BS_, 256>>>(v_att);
    softmax_kernel<<<64, 256>>>();

    // dna pre-GEMMs (split W_dna by row halves; doc+topic combined)
    sgemm128<false, false><<<dim3(D_/128, BS_/128), 256>>>(
        p_sr, W_dna, nullptr, p_sdna,
        nullptr, nullptr, nullptr, BS_, D_, H2);
    sgemm128<false, false><<<dim3(D_/128, (MCMB+127)/128), 256>>>(
        p_cmb, W_dna + (size_t)H2*D_, nullptr, p_cdna,
        nullptr, nullptr, nullptr, MCMB, D_, H2);

    final_fused<<<BS_, 256>>>(b_dna, W_out, b_out, out);
}

// round 17
// speedup vs baseline: 1.2686x; 1.0537x over previous
#include <cuda_runtime.h>
#include <math.h>

#define B_ 32
#define S_ 256
#define L_ 24
#define E_ 300
#define E_P 304          // E padded to multiple of 8 for GEMM
#define H_ 256
#define T_ 16
#define D_ 256
#define BS_ (B_*S_)      // 8192
#define G3H (3*H_)       // 768
#define H2 (2*H_)        // 512
#define H4 (4*H_)        // 1024
#define GRU_NBLK 128     // 64 per direction (R13 proven shape)
#define MCMB (B_*T_ + B_) // 544 combined topic+doc rows
#define HP 34            // smem pitch (4B-word stride 2*ks mod 32 -> conflict-free)

typedef unsigned long long ull;

// ---- packed f32x2 helpers (Blackwell dual-fp32; validated exact in R9) ----
#define FMA2(d, a, b) asm("fma.rn.f32x2 %0, %1, %2, %0;" : "+l"(d) : "l"(a), "l"(b))
#define ADD2(d, a, b) asm("add.rn.f32x2 %0, %1, %2;" : "=l"(d) : "l"(a), "l"(b))
__device__ __forceinline__ ull pack2(float v) {
    ull d; unsigned u = __float_as_uint(v);
    asm("mov.b64 %0, {%1, %1};" : "=l"(d) : "r"(u));
    return d;
}
__device__ __forceinline__ void unpack2(ull v, float& lo, float& hi) {
    unsigned a, b;
    asm("mov.b64 {%0, %1}, %2;" : "=r"(a), "=r"(b) : "l"(v));
    lo = __uint_as_float(a); hi = __uint_as_float(b);
}

// ------------------------- scratch (device globals; no runtime allocs) ----
__device__ float g_sent_vecs[BS_*E_P];
__device__ float g_WihT[2][E_P*G3H];
__device__ float g_gi[2][BS_*G3H];
__device__ float g_sent_rep[BS_*H2];
__device__ float g_h[2][2][H_*B_];        // TRANSPOSED: [dir][buf][c*32 + b]
__device__ float g_hT[2][B_*H_];          // b-major final hidden
__device__ float g_cmb[MCMB*H2];          // rows 0..511 topic_mat, 512..543 doc_vec
__device__ int   g_topic_id[BS_];
__device__ float g_sent_part[BS_*H4];     // sent_rep @ W_att[512:]
__device__ float g_part[MCMB*H4];         // cmb @ W_att[:512]
__device__ float g_sent_dna[BS_*D_];      // sent_rep @ W_dna[:512]
__device__ float g_cmb_dna[MCMB*D_];      // cmb @ W_dna[512:]
__device__ float g_sc[2][BS_];
__device__ float g_w[2][BS_];
// monotonic barrier sub-counters: [dir][sub], each on its own 128B line
__device__ unsigned g_cnt[2][8][32];

// ------------------------------------------------------------------- init
__global__ void init_kernel() {
    int idx = blockIdx.x * blockDim.x + threadIdx.x;
    if (idx < 2*2*H_*B_) ((float*)g_h)[idx] = 0.f;
    if (idx < 16) g_cnt[idx >> 3][idx & 7][0] = 0u;
}

// ------------------------------------------------- transpose Wih -> [E_P,3H]
__global__ void transpose_wih(const float* __restrict__ Wf,
                              const float* __restrict__ Wb) {
    int idx = blockIdx.x * blockDim.x + threadIdx.x;
    if (idx < E_P * G3H) {
        int c = idx / G3H, r = idx % G3H;
        float vf = 0.f, vb = 0.f;
        if (c < E_) { vf = Wf[r*E_ + c]; vb = Wb[r*E_ + c]; }
        g_WihT[0][c*G3H + r] = vf;
        g_WihT[1][c*G3H + r] = vb;
    }
}

// --------------------- sent_vecs = mean over L embeddings (float4 gathers)
__global__ void embed_mean(const int* __restrict__ wid,
                           const float* __restrict__ emb) {
    int bs = blockIdx.x;
    __shared__ int sw[L_];
    if (threadIdx.x < L_) sw[threadIdx.x] = wid[bs*L_ + threadIdx.x];
    __syncthreads();
    const float inv = 1.f / (float)L_;
    for (int c4 = threadIdx.x; c4 < E_P/4; c4 += blockDim.x) {
        float4 s = make_float4(0.f, 0.f, 0.f, 0.f);
        if (c4 < E_/4) {
#pragma unroll
            for (int l = 0; l < L_; l++) {
                float4 v = __ldg((const float4*)(emb + (size_t)sw[l]*E_) + c4);
                s.x += v.x; s.y += v.y; s.z += v.z; s.w += v.w;
            }
            s.x *= inv; s.y *= inv; s.z *= inv; s.w *= inv;
        }
        *(float4*)(g_sent_vecs + (size_t)bs*E_P + c4*4) = s;
    }
}

// ------------------------------------------------------------- SGEMM 128x128
// (scalar FFMA — proven at 94% of FFMA-issue roofline)
// DUAL: gridDim.z selects (Bm,bias,C) pair (used for the gi GEMM).
// NSPLIT: blockIdx.x tile-range selects operand set (N-concat of two GEMMs
//         sharing the same A; saves a launch + re-reading A).
template<bool HASB, bool DUAL, int NT0>
__global__ void __launch_bounds__(256)
sgemm128(const float* __restrict__ A, const float* __restrict__ Bm0,
         const float* __restrict__ bias0, float* __restrict__ C0, int N0,
         const float* __restrict__ Bm1, const float* __restrict__ bias1,
         float* __restrict__ C1, int N1, int M, int K) {
    bool sel;
    int bn, N;
    const float *Bm, *bias;
    float* C;
    if (DUAL) {
        sel = (blockIdx.z != 0);
        bn = blockIdx.x * 128;
    } else {
        sel = ((int)blockIdx.x >= NT0);
        bn = (sel ? (int)blockIdx.x - NT0 : (int)blockIdx.x) * 128;
    }
    Bm = sel ? Bm1 : Bm0; bias = sel ? bias1 : bias0;
    C = sel ? C1 : C0;    N = sel ? N1 : N0;

    __shared__ float As[2][8][128];
    __shared__ float Bs[2][8][128];
    const int tid = threadIdx.x;
    const int bm = blockIdx.y * 128;
    const int tx = tid & 15, ty = tid >> 4;
    const int aRow = tid >> 1, aCol = (tid & 1) * 4;
    const int bRow = tid >> 5, bCol = (tid & 31) * 4;
    const bool aValid = (bm + aRow) < M;
    const float* Aptr = A + (size_t)(bm + aRow) * K + aCol;
    const float* Bptr = Bm + (size_t)bRow * N + bn + bCol;

    float acc[8][8];
#pragma unroll
    for (int i = 0; i < 8; i++)
#pragma unroll
        for (int j = 0; j < 8; j++) acc[i][j] = 0.f;

    float4 av = aValid ? *(const float4*)Aptr : make_float4(0.f,0.f,0.f,0.f);
    float4 bv = *(const float4*)Bptr;
    As[0][aCol+0][aRow] = av.x; As[0][aCol+1][aRow] = av.y;
    As[0][aCol+2][aRow] = av.z; As[0][aCol+3][aRow] = av.w;
    *(float4*)&Bs[0][bRow][bCol] = bv;
    __syncthreads();

    const int nStages = K >> 3;
    for (int s = 0; s < nStages; s++) {
        const int cur = s & 1, nxt = cur ^ 1;
        if (s + 1 < nStages) {
            av = aValid ? *(const float4*)(Aptr + (s+1)*8)
                        : make_float4(0.f,0.f,0.f,0.f);
            bv = *(const float4*)(Bptr + (size_t)(s+1)*8*N);
        }
#pragma unroll
        for (int kk = 0; kk < 8; kk++) {
            float4 a0 = *(const float4*)&As[cur][kk][ty*8];
            float4 a1 = *(const float4*)&As[cur][kk][ty*8+4];
            float4 b0 = *(const float4*)&Bs[cur][kk][tx*8];
            float4 b1 = *(const float4*)&Bs[cur][kk][tx*8+4];
            float a[8] = {a0.x,a0.y,a0.z,a0.w,a1.x,a1.y,a1.z,a1.w};
            float b[8] = {b0.x,b0.y,b0.z,b0.w,b1.x,b1.y,b1.z,b1.w};
#pragma unroll
            for (int i = 0; i < 8; i++)
#pragma unroll
                for (int j = 0; j < 8; j++) acc[i][j] += a[i]*b[j];
        }
        if (s + 1 < nStages) {
            As[nxt][aCol+0][aRow] = av.x; As[nxt][aCol+1][aRow] = av.y;
            As[nxt][aCol+2][aRow] = av.z; As[nxt][aCol+3][aRow] = av.w;
            *(float4*)&Bs[nxt][bRow][bCol] = bv;
        }
        __syncthreads();
    }

#pragma unroll
    for (int i = 0; i < 8; i++) {
        int m = bm + ty*8 + i;
        if (m < M) {
            float4 o0, o1;
#pragma unroll
            for (int j = 0; j < 8; j++) {
                float v = acc[i][j];
                if (HASB) v += bias[bn + tx*8 + j];
                if (j < 4) ((float*)&o0)[j] = v; else ((float*)&o1)[j-4] = v;
            }
            *(float4*)&C[(size_t)m*N + bn + tx*8]     = o0;
            *(float4*)&C[(size_t)m*N + bn + tx*8 + 4] = o1;
        }
    }
}

// --------------------------------------------------- persistent GRU kernel
// == R16 verbatim (best passing: writer-only fence, deferred sent_rep).
__global__ void __launch_bounds__(256) gru_kernel(
    const float* __restrict__ Whh_f, const float* __restrict__ Whh_b,
    const float* __restrict__ bhh_f, const float* __restrict__ bhh_b) {
    __shared__ float sh[H_ * HP];              // sh[k*HP + b], pitch 34
    const int tid = threadIdx.x;
    const int blk = blockIdx.x;
    const int dir = blk >> 6;                  // 0 fwd, 1 bwd
    const int dblk = blk & 63;
    const int cb  = dblk * 4;                  // 4 hidden cols per block
    const int bg  = tid >> 6;                  // 0..3 (batch group of 8)
    const int q   = (tid >> 4) & 3;            // 0..3 (local column)
    const int ks  = tid & 15;                  // 0..15 (k slice)
    const float* Whh = dir ? Whh_b : Whh_f;
    const float* bhh = dir ? bhh_b : bhh_f;
    const float* gi  = g_gi[dir];
    const int j = cb + q;

    ull w2[3][16];
#pragma unroll
    for (int ki = 0; ki < 16; ki++) {
        int kk = ks + 16*ki;
        w2[0][ki] = pack2(Whh[(0*H_ + j)*H_ + kk]);
        w2[1][ki] = pack2(Whh[(1*H_ + j)*H_ + kk]);
        w2[2][ki] = pack2(Whh[(2*H_ + j)*H_ + kk]);
    }
    const float bb0 = bhh[j], bb1 = bhh[H_ + j], bb2 = bhh[2*H_ + j];
    const bool wr = (ks < 4);
    const int bp = bg*8 + 2*ks;                // batch pair base (writers)

    volatile unsigned* cc[8];
#pragma unroll
    for (int u = 0; u < 8; u++) cc[u] = &g_cnt[dir][u][0];

    for (int i = 0; i < S_; i++) {
        const int t = dir ? (S_ - 1 - i) : i;
        const int cur = i & 1, nxt = cur ^ 1;

        float gir0=0.f, giz0=0.f, gin0=0.f, gir1=0.f, giz1=0.f, gin1=0.f;
        int row0 = 0, row1 = 0;
        if (wr) {
            row0 = bp*S_ + t; row1 = (bp+1)*S_ + t;
            gir0 = __ldg(&gi[(size_t)row0*G3H + j]);
            giz0 = __ldg(&gi[(size_t)row0*G3H + H_ + j]);
            gin0 = __ldg(&gi[(size_t)row0*G3H + 2*H_ + j]);
            gir1 = __ldg(&gi[(size_t)row1*G3H + j]);
            giz1 = __ldg(&gi[(size_t)row1*G3H + H_ + j]);
            gin1 = __ldg(&gi[(size_t)row1*G3H + 2*H_ + j]);
        }

        const float4* hb = (const float4*)g_h[dir][cur];
#pragma unroll
        for (int xi = 0; xi < 8; xi++) {
            int x = xi*256 + tid;              // float4 index, 2048 total
            float4 v = __ldcg(hb + x);
            int c = x >> 3, b4 = (x & 7) * 4;
            float* d = &sh[c*HP + b4];         // even offset -> float2 ok
            *(float2*)(d)     = make_float2(v.x, v.y);
            *(float2*)(d + 2) = make_float2(v.z, v.w);
        }
        __syncthreads();

        ull acc[4][3];
#pragma unroll
        for (int p = 0; p < 4; p++) { acc[p][0]=0ull; acc[p][1]=0ull; acc[p][2]=0ull; }
#pragma unroll
        for (int ki = 0; ki < 16; ki++) {
            int kk = ks + 16*ki;
            const ull* hrow = (const ull*)&sh[kk*HP + bg*8];
#pragma unroll
            for (int p = 0; p < 4; p++) {
                ull h2 = hrow[p];
                FMA2(acc[p][0], h2, w2[0][ki]);
                FMA2(acc[p][1], h2, w2[1][ki]);
                FMA2(acc[p][2], h2, w2[2][ki]);
            }
        }
#pragma unroll
        for (int m = 1; m < 16; m <<= 1) {
#pragma unroll
            for (int p = 0; p < 4; p++) {
#pragma unroll
                for (int g = 0; g < 3; g++) {
                    ull o = __shfl_xor_sync(0xffffffffu, acc[p][g], m);
                    ADD2(acc[p][g], acc[p][g], o);
                }
            }
        }
        float h0 = 0.f, h1 = 0.f;
        if (wr) {
            ull ar = (ks==0)?acc[0][0]:(ks==1)?acc[1][0]:(ks==2)?acc[2][0]:acc[3][0];
            ull az = (ks==0)?acc[0][1]:(ks==1)?acc[1][1]:(ks==2)?acc[2][1]:acc[3][1];
            ull an = (ks==0)?acc[0][2]:(ks==1)?acc[1][2]:(ks==2)?acc[2][2]:acc[3][2];
            float gr0, gr1, gz0, gz1, gn0, gn1;
            unpack2(ar, gr0, gr1); unpack2(az, gz0, gz1); unpack2(an, gn0, gn1);

            const float2 hold = *(const float2*)&sh[j*HP + bp];

            const float r0 = 1.f / (1.f + __expf(-(gir0 + gr0 + bb0)));
            const float z0 = 1.f / (1.f + __expf(-(giz0 + gz0 + bb1)));
            const float n0 = tanhf(gin0 + r0 * (gn0 + bb2));
            h0 = (1.f - z0)*n0 + z0*hold.x;

            const float r1 = 1.f / (1.f + __expf(-(gir1 + gr1 + bb0)));
            const float z1 = 1.f / (1.f + __expf(-(giz1 + gz1 + bb1)));
            const float n1 = tanhf(gin1 + r1 * (gn1 + bb2));
            h1 = (1.f - z1)*n1 + z1*hold.y;

            __stcg((float2*)&g_h[dir][nxt][j*32 + bp], make_float2(h0, h1));
        }
        if (i != S_-1) {
            if (wr) __threadfence();
            __syncthreads();
            if (tid == 0) atomicAdd(&g_cnt[dir][dblk & 7][0], 1u);
            if (wr) {
                g_sent_rep[(size_t)row0*H2 + dir*H_ + j] = h0;
                g_sent_rep[(size_t)row1*H2 + dir*H_ + j] = h1;
            }
            if (tid == 0) {
                const unsigned target = (unsigned)(i + 1) * 8u;
                unsigned v0,v1,v2,v3,v4,v5,v6,v7;
                do {
                    v0 = *cc[0]; v1 = *cc[1]; v2 = *cc[2]; v3 = *cc[3];
                    v4 = *cc[4]; v5 = *cc[5]; v6 = *cc[6]; v7 = *cc[7];
                } while (v0 < target || v1 < target || v2 < target ||
                         v3 < target || v4 < target || v5 < target ||
                         v6 < target || v7 < target);
            }
            __syncthreads();
        } else if (wr) {
            g_sent_rep[(size_t)row0*H2 + dir*H_ + j] = h0;
            g_sent_rep[(size_t)row1*H2 + dir*H_ + j] = h1;
            g_hT[dir][bp*H_ + j]     = h0;
            g_hT[dir][(bp+1)*H_ + j] = h1;
        }
    }
}

// ----------------------------- combined (topic_mat ++ doc_vec) + topic_id
__global__ void prep_kernel(const int* __restrict__ tse) {
    const int gstride = gridDim.x * blockDim.x;
    const int gtid = blockIdx.x * blockDim.x + threadIdx.x;
    for (int idx = gtid; idx < B_*H2; idx += gstride) {
        int d = idx >> 13; int rem = idx & 8191;
        g_cmb[B_*T_*H2 + idx] = g_hT[d][rem];
    }
    for (int idx = gtid; idx < B_*T_*H2; idx += gstride) {
        int c = idx & 511; int t = (idx >> 9) & 15; int b = idx >> 13;
        int st = tse[(b*T_ + t)*2 + 0], en = tse[(b*T_ + t)*2 + 1];
        int p1, p2;
        if (c < H_) { p1 = en;  p2 = st - 1; }
        else        { p1 = st;  p2 = en + 1; }
        p1 = min(max(p1, 0), S_+1); p2 = min(max(p2, 0), S_+1);
        float v1 = (p1 >= 1 && p1 <= S_) ? g_sent_rep[(size_t)(b*S_ + p1-1)*H2 + c] : 0.f;
        float v2 = (p2 >= 1 && p2 <= S_) ? g_sent_rep[(size_t)(b*S_ + p2-1)*H2 + c] : 0.f;
        g_cmb[idx] = v1 - v2;
    }
    for (int idx = gtid; idx < BS_; idx += gstride) {
        int b = idx >> 8, s = idx & 255;
        int t = 0;
        while (t < T_ && tse[(b*T_ + t)*2 + 1] < s + 1) t++;
        if (t >= T_) t = T_ - 1;
        g_topic_id[idx] = t;
    }
}

// ---------------- fused: scores = tanh(sent_part + {doc|topic}_part) . v
__global__ void __launch_bounds__(256) score_fused(const float* __restrict__ v) {
    const int row = blockIdx.x;
    const int b = row >> 8;
    const int bt = b*T_ + g_topic_id[row];
    const float* sp = &g_sent_part[(size_t)row*H4];
    const float* dp = &g_part[(size_t)(B_*T_ + b)*H4];
    const float* tp = &g_part[(size_t)bt*H4];
    float s0 = 0.f, s1 = 0.f;
    for (int c = threadIdx.x; c < H4; c += 256) {
        float s = sp[c], vv = v[c];
        s0 += tanhf(s + dp[c]) * vv;
        s1 += tanhf(s + tp[c]) * vv;
    }
    __shared__ float r0[256], r1[256];
    r0[threadIdx.x] = s0; r1[threadIdx.x] = s1;
    __syncthreads();
    for (int m = 128; m; m >>= 1) {
        if (threadIdx.x < m) {
            r0[threadIdx.x] += r0[threadIdx.x + m];
            r1[threadIdx.x] += r1[threadIdx.x + m];
        }
        __syncthreads();
    }
    if (threadIdx.x == 0) { g_sc[0][row] = r0[0]; g_sc[1][row] = r1[0]; }
}

// ------------------------------------------------------ softmax over S
__global__ void softmax_kernel() {
    const int type = blockIdx.x >> 5, b = blockIdx.x & 31;
    const int s = threadIdx.x;
    __shared__ float sm[256];
    float x = g_sc[type][b*S_ + s];
    sm[s] = x; __syncthreads();
    for (int m = 128; m; m >>= 1) { if (s < m) sm[s] = fmaxf(sm[s], sm[s + m]); __syncthreads(); }
    float mx = sm[0]; __syncthreads();
    float e = __expf(x - mx);
    sm[s] = e; __syncthreads();
    for (int m = 128; m; m >>= 1) { if (s < m) sm[s] += sm[s + m]; __syncthreads(); }
    g_w[type][b*S_ + s] = e / sm[0];
}

// ------ fused: h=relu(sent_dna + wd*doc_dna + wt*topic_dna + b); out=h.Wout
__global__ void __launch_bounds__(256) final_fused(
    const float* __restrict__ b_dna, const float* __restrict__ Wout,
    const float* __restrict__ bout, float* __restrict__ out) {
    const int row = blockIdx.x;
    const int b = row >> 8;
    const int bt = b*T_ + g_topic_id[row];
    const int c = threadIdx.x;
    const float wd = g_w[0][row], wt = g_w[1][row];
    float h = g_sent_dna[(size_t)row*D_ + c]
            + wd * g_cmb_dna[(size_t)(B_*T_ + b)*D_ + c]
            + wt * g_cmb_dna[(size_t)bt*D_ + c]
            + b_dna[c];
    h = fmaxf(h, 0.f);
    float s = h * Wout[c];
    __shared__ float r[256];
    r[c] = s; __syncthreads();
    for (int m = 128; m; m >>= 1) {
        if (c < m) r[c] += r[c + m];
        __syncthreads();
    }
    if (c == 0) out[row] = r[0] + bout[0];
}

// ------------------------------------------------------------------ host
extern "C" void kernel_launch(void* const* d_in, const int* in_sizes, int n_in,
                              void* d_out, int out_size) {
    const int*   word_ids = (const int*)  d_in[0];
    const int*   tse      = (const int*)  d_in[1];
    const float* emb      = (const float*)d_in[2];
    const float* Wih_f    = (const float*)d_in[3];
    const float* Whh_f    = (const float*)d_in[4];
    const float* bih_f    = (const float*)d_in[5];
    const float* bhh_f    = (const float*)d_in[6];
    const float* Wih_b    = (const float*)d_in[7];
    const float* Whh_b    = (const float*)d_in[8];
    const float* bih_b    = (const float*)d_in[9];
    const float* bhh_b    = (const float*)d_in[10];
    const float* W_att    = (const float*)d_in[11];
    const float* v_att    = (const float*)d_in[12];
    const float* W_dna    = (const float*)d_in[13];
    const float* b_dna    = (const float*)d_in[14];
    const float* W_out    = (const float*)d_in[15];
    const float* b_out    = (const float*)d_in[16];
    float* out = (float*)d_out;

    float *p_sv, *p_wt, *p_gi, *p_sr, *p_cmb;
    float *p_spart, *p_part, *p_sdna, *p_cdna;
    cudaGetSymbolAddress((void**)&p_sv,   g_sent_vecs);
    cudaGetSymbolAddress((void**)&p_wt,   g_WihT);
    cudaGetSymbolAddress((void**)&p_gi,   g_gi);
    cudaGetSymbolAddress((void**)&p_sr,   g_sent_rep);
    cudaGetSymbolAddress((void**)&p_cmb,  g_cmb);
    cudaGetSymbolAddress((void**)&p_spart, g_sent_part);
    cudaGetSymbolAddress((void**)&p_part,  g_part);
    cudaGetSymbolAddress((void**)&p_sdna,  g_sent_dna);
    cudaGetSymbolAddress((void**)&p_cdna,  g_cmb_dna);

    init_kernel<<<128, 256>>>();
    transpose_wih<<<(E_P*G3H + 255)/256, 256>>>(Wih_f, Wih_b);
    embed_mean<<<BS_, 96>>>(word_ids, emb);

    // gi = sent_vecs @ Wih^T + bih  (both directions fused via gridDim.z)
    sgemm128<true, true, 0><<<dim3(G3H/128, BS_/128, 2), 256>>>(
        p_sv, p_wt, bih_f, p_gi, G3H,
        p_wt + E_P*G3H, bih_b, p_gi + BS_*G3H, G3H, BS_, E_P);

    gru_kernel<<<GRU_NBLK, 256>>>(Whh_f, Whh_b, bhh_f, bhh_b);

    prep_kernel<<<256, 256>>>(tse);

    // sent_rep GEMMs N-concat: [W_att[512:] (N=1024) | W_dna[:512] (N=256)]
    sgemm128<false, false, H4/128><<<dim3(H4/128 + D_/128, BS_/128), 256>>>(
        p_sr, W_att + (size_t)H2*H4, nullptr, p_spart, H4,
        W_dna, nullptr, p_sdna, D_, BS_, H2);

    // cmb GEMMs N-concat: [W_att[:512] (N=1024) | W_dna[512:] (N=256)]
    sgemm128<false, false, H4/128><<<dim3(H4/128 + D_/128, (MCMB+127)/128), 256>>>(
        p_cmb, W_att, nullptr, p_part, H4,
        W_dna + (size_t)H2*D_, nullptr, p_cdna, D_, MCMB, H2);

    score_fused<<<BS_, 256>>>(v_att);
    softmax_kernel<<<64, 256>>>();

    final_fused<<<BS_, 256>>>(b_dna, W_out, b_out, out);
}